// round 1
// baseline (speedup 1.0000x reference)
#include <cuda_runtime.h>
#include <cstdint>

// CompressedHE: per-channel histogram equalization.
// x: [16,3,1024,1024] fp32 in [0,1)  ->  out same shape fp32.
// 48 channels of 1M pixels each.

#define NCH     48
#define HW      (1 << 20)          // pixels per channel
#define BPC     32                 // blocks per channel (streaming kernels)
#define CHUNK   (HW / BPC)         // 32768 pixels per block
#define THREADS 256

// Scratch (device globals — no allocation allowed in kernel_launch).
__device__ int          g_hist[NCH * 256];
__device__ float        g_lut [NCH * 256];
__device__ unsigned int g_vals[NCH * HW / 4];   // 4 packed u8 bins per word (48 MiB)

__global__ void zero_hist_kernel() {
    int i = blockIdx.x * blockDim.x + threadIdx.x;
    if (i < NCH * 256) g_hist[i] = 0;
}

__global__ void __launch_bounds__(THREADS)
hist_kernel(const float4* __restrict__ x) {
    const int chan = blockIdx.x >> 5;        // / BPC
    const int blk  = blockIdx.x & (BPC - 1);

    __shared__ int sh[256];
    sh[threadIdx.x] = 0;
    __syncthreads();

    const size_t base = (size_t)chan * (HW / 4) + (size_t)blk * (CHUNK / 4);
    const float4* __restrict__ p = x + base;
    unsigned int* __restrict__ q = g_vals + base;

    #pragma unroll 4
    for (int i = threadIdx.x; i < CHUNK / 4; i += THREADS) {
        float4 v = p[i];
        // Truncation toward zero, identical to jnp astype(int32) after *255.0 (fp32).
        int b0 = min(max((int)(v.x * 255.0f), 0), 255);
        int b1 = min(max((int)(v.y * 255.0f), 0), 255);
        int b2 = min(max((int)(v.z * 255.0f), 0), 255);
        int b3 = min(max((int)(v.w * 255.0f), 0), 255);
        q[i] = (unsigned)b0 | ((unsigned)b1 << 8) |
               ((unsigned)b2 << 16) | ((unsigned)b3 << 24);
        atomicAdd(&sh[b0], 1);
        atomicAdd(&sh[b1], 1);
        atomicAdd(&sh[b2], 1);
        atomicAdd(&sh[b3], 1);
    }
    __syncthreads();

    int c = sh[threadIdx.x];
    if (c) atomicAdd(&g_hist[chan * 256 + threadIdx.x], c);
}

// One thread per channel: find last occupied bin, build shifted-cumsum LUT,
// pre-divide by 255 so the apply pass is a pure gather.
__global__ void lut_kernel() {
    int c = blockIdx.x * blockDim.x + threadIdx.x;
    if (c >= NCH) return;

    const int* __restrict__ h = &g_hist[c * 256];
    int last_cnt = 0;
    #pragma unroll 8
    for (int b = 0; b < 256; b++) {
        int v = h[b];
        if (v > 0) last_cnt = v;       // sum(hist) == HW always
    }
    int step = (HW - last_cnt) / 255;  // integer floor div, nonnegative

    float* __restrict__ lf = &g_lut[c * 256];
    if (step == 0) {
        // Pass the quantized pixel value through: out = b / 255.
        for (int b = 0; b < 256; b++) lf[b] = (float)b * (1.0f / 255.0f);
    } else {
        const int half = step >> 1;    // safe_step // 2
        int cum = 0;
        lf[0] = 0.0f;                  // prepended zero (shift-right by one bin)
        for (int b = 1; b < 256; b++) {
            cum += h[b - 1];
            int l = (cum + half) / step;
            if (l > 255) l = 255;      // clip (lower bound 0 is automatic)
            lf[b] = (float)l * (1.0f / 255.0f);
        }
    }
}

__global__ void __launch_bounds__(THREADS)
apply_kernel(float4* __restrict__ out) {
    const int chan = blockIdx.x >> 5;
    const int blk  = blockIdx.x & (BPC - 1);

    __shared__ float slut[256];
    slut[threadIdx.x] = g_lut[chan * 256 + threadIdx.x];
    __syncthreads();

    const size_t base = (size_t)chan * (HW / 4) + (size_t)blk * (CHUNK / 4);
    const unsigned int* __restrict__ q = g_vals + base;
    float4* __restrict__ o = out + base;

    #pragma unroll 4
    for (int i = threadIdx.x; i < CHUNK / 4; i += THREADS) {
        unsigned w = q[i];
        float4 r;
        r.x = slut[w & 255u];
        r.y = slut[(w >> 8) & 255u];
        r.z = slut[(w >> 16) & 255u];
        r.w = slut[w >> 24];
        o[i] = r;
    }
}

extern "C" void kernel_launch(void* const* d_in, const int* in_sizes, int n_in,
                              void* d_out, int out_size) {
    const float4* x = (const float4*)d_in[0];
    float4* out = (float4*)d_out;

    zero_hist_kernel<<<(NCH * 256 + 255) / 256, 256>>>();
    hist_kernel<<<NCH * BPC, THREADS>>>(x);
    lut_kernel<<<1, 64>>>();
    apply_kernel<<<NCH * BPC, THREADS>>>(out);
}